// round 13
// baseline (speedup 1.0000x reference)
#include <cuda_runtime.h>
#include <cuda_fp16.h>
#include <cstdint>
#include <math.h>

#define B_ 4
#define S_ 4096
#define D_ 1024
#define H_ 16
#define HD_ 64
#define M_ (B_*S_)          // 16384
#define BH_ (B_*H_)         // 64
#define SPLIT_ 16

// GEMM tiling (fp16 mma.sync m16n8k16, fp32 accumulate)
#define TMM 64                      // M tile (was 128) -> 3 blocks/SM
#define TNN 128                     // N tile
#define BKH 64                      // halves per K-chunk = 128B row
#define NCH (D_/BKH)                // 16 chunks
#define PITCHB 160                  // bytes per smem row (bank-clean per 16-lane phase)
#define ASTG (64*PITCHB)            // 10240
#define BSTG (128*PITCHB)           // 20480
#define STG_TOT (ASTG+BSTG)         // 30720
#define SMEM_BYTES (2*STG_TOT)      // 61440 -> 3 blocks/SM

// mid-section smem pitch: 144B per 72-half row -> conflict-free ldmatrix
#define MPITCH 144

// ---------------- scratch (device globals; no allocation) ----------------
__device__ __align__(16) __half g_Qh[(size_t)M_ * D_];  // [bh][s][d] fp16
__device__ __align__(16) __half g_Kh[(size_t)M_ * D_];
__device__ __align__(16) __half g_Vh[(size_t)M_ * D_];
__device__ __align__(16) __half g_O[(size_t)M_ * D_];   // [b,s,1024] fp16+perm
__device__ __align__(16) __half g_Ah[3][(size_t)M_ * D_]; // fp16+perm activations
__device__ __align__(16) __half g_Wh[4][(size_t)D_ * D_]; // fp16+perm weights
__device__ __align__(16) float  g_KVpart[(size_t)BH_ * SPLIT_ * HD_ * 72];
__device__ __align__(16) __half g_KVh[(size_t)BH_ * HD_ * 72]; // 0-63 KV, 64 KS

// ---------------- helpers ----------------
__device__ __forceinline__ uint32_t smem_u32(const void* p) {
    uint32_t a;
    asm("{ .reg .u64 t; cvta.to.shared.u64 t, %1; cvt.u32.u64 %0, t; }" : "=r"(a) : "l"(p));
    return a;
}
#define CP16(dst, src) asm volatile("cp.async.cg.shared.global [%0], [%1], 16;" :: "r"(dst), "l"(src))
#define CP_COMMIT()    asm volatile("cp.async.commit_group;" ::: "memory")
#define CP_WAIT1()     asm volatile("cp.async.wait_group 1;" ::: "memory")
#define CP_WAIT0()     asm volatile("cp.async.wait_group 0;" ::: "memory")

#define MMA_F16(c, a, b) \
    asm volatile("mma.sync.aligned.m16n8k16.row.col.f32.f16.f16.f32 " \
        "{%0,%1,%2,%3}, {%4,%5,%6,%7}, {%8,%9}, {%0,%1,%2,%3};" \
        : "+f"((c)[0]), "+f"((c)[1]), "+f"((c)[2]), "+f"((c)[3]) \
        : "r"((a)[0]), "r"((a)[1]), "r"((a)[2]), "r"((a)[3]), \
          "r"((b)[0]), "r"((b)[1]))

#define LDSM_X4(r0, r1, r2, r3, addr) \
    asm volatile("ldmatrix.sync.aligned.m8n8.x4.shared.b16 {%0,%1,%2,%3}, [%4];" \
        : "=r"(r0), "=r"(r1), "=r"(r2), "=r"(r3) : "r"(addr))
#define LDSM_X4_T(r0, r1, r2, r3, addr) \
    asm volatile("ldmatrix.sync.aligned.m8n8.x4.trans.shared.b16 {%0,%1,%2,%3}, [%4];" \
        : "=r"(r0), "=r"(r1), "=r"(r2), "=r"(r3) : "r"(addr))
#define LDSM_X2_T(r0, r1, addr) \
    asm volatile("ldmatrix.sync.aligned.m8n8.x2.trans.shared.b16 {%0,%1}, [%2];" \
        : "=r"(r0), "=r"(r1) : "r"(addr))

__device__ __forceinline__ uint32_t pack_h2(float lo, float hi) {
    __half2 h = __floats2half2_rn(lo, hi);
    return *reinterpret_cast<uint32_t*>(&h);
}

// ---------------------------------------------------------------------------
// fp32 -> fp16 RN + pair-permute within 16-groups: pairs out {0,4,1,5,2,6,3,7}
// ---------------------------------------------------------------------------
__device__ __forceinline__ void conv_body(const float4* __restrict__ src,
                                          uint4* __restrict__ dst, int i)
{
    float4 v0 = src[4 * i], v1 = src[4 * i + 1], v2 = src[4 * i + 2], v3 = src[4 * i + 3];
    uint4 o0, o1;
    o0.x = pack_h2(v0.x, v0.y);   o0.y = pack_h2(v2.x, v2.y);
    o0.z = pack_h2(v0.z, v0.w);   o0.w = pack_h2(v2.z, v2.w);
    o1.x = pack_h2(v1.x, v1.y);   o1.y = pack_h2(v3.x, v3.y);
    o1.z = pack_h2(v1.z, v1.w);   o1.w = pack_h2(v3.z, v3.w);
    dst[2 * i] = o0;  dst[2 * i + 1] = o1;
}

__global__ void conv_act_kernel(const float4* __restrict__ q, const float4* __restrict__ k,
                                const float4* __restrict__ v)
{
    int i = blockIdx.x * blockDim.x + threadIdx.x;
    const int n16 = M_ * D_ / 16;
    if (i < n16) {
        const float4* src = (blockIdx.y == 0) ? q : (blockIdx.y == 1) ? k : v;
        conv_body(src, (uint4*)(g_Ah[blockIdx.y]), i);
    }
}

__global__ void conv_w_kernel(const float4* __restrict__ w0, const float4* __restrict__ w1,
                              const float4* __restrict__ w2, const float4* __restrict__ w3)
{
    int i = blockIdx.x * blockDim.x + threadIdx.x;
    const int n16 = D_ * D_ / 16;
    if (i < n16) {
        const float4* src = (blockIdx.y == 0) ? w0 : (blockIdx.y == 1) ? w1
                          : (blockIdx.y == 2) ? w2 : w3;
        conv_body(src, (uint4*)(g_Wh[blockIdx.y]), i);
    }
}

// ---------------------------------------------------------------------------
// Shared GEMM mainloop: 64x128 tile, 2-stage cp.async, tail-drained.
// acc[2][4][4]; warp = 32(m) x {8,8,8,8 at stride 32}(n).
// ---------------------------------------------------------------------------
__device__ __forceinline__ void gemm_mainloop(
    const __half* __restrict__ Ap, const __half* __restrict__ Wp,
    uint32_t sm_u, char* sm, int tid, int m0, int n0,
    int lane, int wid, float acc[2][4][4])
{
    const int wm32 = (wid & 1) * 32;
    const int wn8  = (wid >> 1) * 8;
    const int qrow = lane >> 2;
    const int qcol = lane & 3;

    auto load_chunk = [&](int ch, int st) {
        const int k0 = ch * BKH;
        const uint32_t aB = sm_u + (uint32_t)st * STG_TOT;
        const uint32_t bB = aB + ASTG;
#pragma unroll
        for (int j = 0; j < 2; j++) {                 // A: 64 rows x 8 x 16B
            int q = tid + j * 256, row = q >> 3, seg = q & 7;
            CP16(aB + (uint32_t)(row * PITCHB + seg * 16),
                 Ap + (size_t)(m0 + row) * D_ + k0 + seg * 8);
        }
#pragma unroll
        for (int j = 0; j < 4; j++) {                 // B: 128 rows x 8 x 16B
            int q = tid + j * 256, row = q >> 3, seg = q & 7;
            CP16(bB + (uint32_t)(row * PITCHB + seg * 16),
                 Wp + (size_t)(n0 + row) * D_ + k0 + seg * 8);
        }
    };

    load_chunk(0, 0); CP_COMMIT();
    load_chunk(1, 1); CP_COMMIT();

    for (int i = 0; i < NCH; i++) {
        if (i == NCH - 1) CP_WAIT0();    // tail: drain everything
        else              CP_WAIT1();
        __syncthreads();

        const int st = i & 1;
        const char* As = sm + (size_t)st * STG_TOT;
        const char* Bs = As + ASTG;
#pragma unroll
        for (int kk = 0; kk < 4; kk++) {
            uint32_t bf[4][2];
#pragma unroll
            for (int nt = 0; nt < 4; nt++) {
                uint2 bv = *(const uint2*)(Bs + (wn8 + nt * 32 + qrow) * PITCHB + kk * 32 + 8 * qcol);
                bf[nt][0] = bv.x;  bf[nt][1] = bv.y;
            }
#pragma unroll
            for (int mt = 0; mt < 2; mt++) {
                const char* ap = As + (wm32 + mt * 16 + qrow) * PITCHB + kk * 32 + 8 * qcol;
                uint2 alo = *(const uint2*)ap;
                uint2 ahi = *(const uint2*)(ap + 8 * PITCHB);
                uint32_t af[4] = {alo.x, ahi.x, alo.y, ahi.y};
#pragma unroll
                for (int nt = 0; nt < 4; nt++) MMA_F16(acc[mt][nt], af, bf[nt]);
            }
        }

        if (i + 2 < NCH) {
            __syncthreads();
            load_chunk(i + 2, st);
            CP_COMMIT();
        }
    }
}

// ---------------------------------------------------------------------------
// Fused QKV projection GEMM: blockIdx.z selects {Q,K,V}.
// z=0/1: rope+elu -> g_Qh/g_Kh ; z=2: bias -> g_Vh
// ---------------------------------------------------------------------------
__global__ __launch_bounds__(256, 3)
void gemm_qkv(const float* __restrict__ bq, const float* __restrict__ bk,
              const float* __restrict__ bv,
              const float* __restrict__ cs, const float* __restrict__ sn)
{
    extern __shared__ __align__(16) char sm[];
    const int tid = threadIdx.x;
    const int z   = blockIdx.z;
    const int n0  = blockIdx.x * TNN;
    const int m0  = blockIdx.y * TMM;
    const int lane = tid & 31, wid = tid >> 5;
    const uint32_t sm_u = smem_u32(sm);
    const float* bias = (z == 0) ? bq : (z == 1) ? bk : bv;

    float acc[2][4][4];
#pragma unroll
    for (int mt = 0; mt < 2; mt++)
#pragma unroll
        for (int nt = 0; nt < 4; nt++)
#pragma unroll
            for (int r = 0; r < 4; r++) acc[mt][nt][r] = 0.f;

    gemm_mainloop(g_Ah[z], g_Wh[z], sm_u, sm, tid, m0, n0, lane, wid, acc);

    const int wm32 = (wid & 1) * 32;
    const int wn8  = (wid >> 1) * 8;
    const int qrow = lane >> 2;
    const int qcol = lane & 3;

#pragma unroll
    for (int mt = 0; mt < 2; mt++) {
#pragma unroll
        for (int r = 0; r < 4; r++) {
            const int row = wm32 + mt * 16 + qrow + (r >> 1) * 8;
            const int m = m0 + row;
            const int b = m >> 12;
            const int s = m & (S_ - 1);
            const int cc = 2 * qcol + (r & 1);

            if (z == 2) {
#pragma unroll
                for (int nt = 0; nt < 4; nt++) {
                    int col = wn8 + nt * 32 + cc;
                    int h = (n0 + col) >> 6, e = col & 63;
                    g_Vh[(((size_t)b * H_ + h) * S_ + s) * HD_ + e] =
                        __float2half_rn(acc[mt][nt][r] + bias[n0 + col]);
                }
            } else {
                __half* dstb = (z == 0) ? g_Qh : g_Kh;
#pragma unroll
                for (int half = 0; half < 2; half++) {
                    const int p = half * 2;
                    const int h = (n0 >> 6) + half;
                    const int j = wn8 + cc;                      // 0..31
                    float x1 = acc[mt][p][r]     + bias[h * HD_ + j];
                    float x2 = acc[mt][p + 1][r] + bias[h * HD_ + j + 32];
                    float c1 = cs[s * HD_ + j],      s1 = sn[s * HD_ + j];
                    float c2 = cs[s * HD_ + j + 32], s2 = sn[s * HD_ + j + 32];
                    float r1 = x1 * c1 - x2 * s1;
                    float r2 = x2 * c2 + x1 * s2;
                    r1 = (r1 > 0.f) ? (r1 + 1.f) : expf(r1);
                    r2 = (r2 > 0.f) ? (r2 + 1.f) : expf(r2);
                    __half* d = dstb + (((size_t)b * H_ + h) * S_ + s) * HD_;
                    d[j]      = __float2half_rn(fmaxf(r1, 0.01f));
                    d[j + 32] = __float2half_rn(fmaxf(r2, 0.01f));
                }
            }
        }
    }
}

// ---------------------------------------------------------------------------
// Output projection GEMM: out = g_O @ Wo^T + bo  (fp32 out)
// ---------------------------------------------------------------------------
__global__ __launch_bounds__(256, 3)
void gemm_out(const float* __restrict__ bias, float* __restrict__ out)
{
    extern __shared__ __align__(16) char sm[];
    const int tid = threadIdx.x;
    const int n0  = blockIdx.x * TNN;
    const int m0  = blockIdx.y * TMM;
    const int lane = tid & 31, wid = tid >> 5;
    const uint32_t sm_u = smem_u32(sm);

    float acc[2][4][4];
#pragma unroll
    for (int mt = 0; mt < 2; mt++)
#pragma unroll
        for (int nt = 0; nt < 4; nt++)
#pragma unroll
            for (int r = 0; r < 4; r++) acc[mt][nt][r] = 0.f;

    gemm_mainloop(g_O, g_Wh[3], sm_u, sm, tid, m0, n0, lane, wid, acc);

    const int wm32 = (wid & 1) * 32;
    const int wn8  = (wid >> 1) * 8;
    const int qrow = lane >> 2;
    const int qcol = lane & 3;

#pragma unroll
    for (int mt = 0; mt < 2; mt++) {
#pragma unroll
        for (int r = 0; r < 4; r++) {
            const int row = wm32 + mt * 16 + qrow + (r >> 1) * 8;
            const int m = m0 + row;
            const int cc = 2 * qcol + (r & 1);
#pragma unroll
            for (int nt = 0; nt < 4; nt++) {
                int col = wn8 + nt * 32 + cc;
                out[(size_t)m * D_ + n0 + col] = acc[mt][nt][r] + bias[n0 + col];
            }
        }
    }
}

// ---------------------------------------------------------------------------
// kv_kernel: KVpart[bh][sp][d][e] = sum_{s in chunk} K[s][d] * V'[s][e]
// where V' = [V | 1 | 0...0] (ones column 64 -> KS computed by the same MMA).
// ---------------------------------------------------------------------------
__global__ __launch_bounds__(128)
void kv_kernel()
{
    extern __shared__ __align__(16) char kvsm[];
    const int t = threadIdx.x, lane = t & 31, w = t >> 5;
    const int bh = blockIdx.y, sp = blockIdx.x;
    const uint32_t sK = smem_u32(kvsm);
    const uint32_t sV = sK + 256 * MPITCH;

    const __half* Kg = g_Kh + ((size_t)bh * S_ + sp * 256) * HD_;
    const __half* Vg = g_Vh + ((size_t)bh * S_ + sp * 256) * HD_;
#pragma unroll
    for (int j = 0; j < 16; j++) {
        int q = t + j * 128, row = q >> 3, seg = q & 7;
        CP16(sK + row * MPITCH + seg * 16, Kg + row * HD_ + seg * 8);
        CP16(sV + row * MPITCH + seg * 16, Vg + row * HD_ + seg * 8);
    }
    {   // V pad: col 64 = 1.0h, cols 65-71 = 0
        uint4 ones = make_uint4(0x00003C00u, 0u, 0u, 0u);
        *(uint4*)(kvsm + (256 * MPITCH) + (t * 2) * MPITCH + 128) = ones;
        *(uint4*)(kvsm + (256 * MPITCH) + (t * 2 + 1) * MPITCH + 128) = ones;
    }
    CP_COMMIT();
    CP_WAIT0();
    __syncthreads();

    const int g = lane >> 2, cc = lane & 3;
    const int d0 = w * 16;
    const uint32_t aBase = sK + ((lane & 7) + ((lane >> 4) << 3)) * MPITCH
                         + d0 * 2 + ((lane >> 3) & 1) * 16;
    const uint32_t bBase = sV + ((lane & 7) + ((lane >> 3) & 1) * 8) * MPITCH
                         + ((lane >> 4) << 4);
    const uint32_t b8Base = sV + ((lane & 7) + ((lane >> 3) & 1) * 8) * MPITCH + 128;

    float c[9][4];
#pragma unroll
    for (int nt = 0; nt < 9; nt++)
#pragma unroll
        for (int r = 0; r < 4; r++) c[nt][r] = 0.f;

#pragma unroll 4
    for (int s0 = 0; s0 < 256; s0 += 16) {
        uint32_t af[4];
        LDSM_X4_T(af[0], af[1], af[2], af[3], aBase + s0 * MPITCH);
#pragma unroll
        for (int nt2 = 0; nt2 < 4; nt2++) {
            uint32_t b0, b1, b2, b3;
            LDSM_X4_T(b0, b1, b2, b3, bBase + s0 * MPITCH + nt2 * 32);
            uint32_t bf0[2] = {b0, b1}, bf1[2] = {b2, b3};
            MMA_F16(c[2 * nt2],     af, bf0);
            MMA_F16(c[2 * nt2 + 1], af, bf1);
        }
        {   // KS tile (cols 64-71; col 64 = ones)
            uint32_t b0, b1;
            LDSM_X2_T(b0, b1, b8Base + s0 * MPITCH);
            uint32_t bf[2] = {b0, b1};
            MMA_F16(c[8], af, bf);
        }
    }

    float* dst = g_KVpart + (((size_t)bh * SPLIT_ + sp) * HD_ + d0 + g) * 72;
#pragma unroll
    for (int nt = 0; nt < 8; nt++) {
        *(float2*)(dst + 8 * nt + 2 * cc) = make_float2(c[nt][0], c[nt][1]);
        *(float2*)(dst + 8 * 72 + 8 * nt + 2 * cc) = make_float2(c[nt][2], c[nt][3]);
    }
    *(float2*)(dst + 64 + 2 * cc) = make_float2(c[8][0], c[8][1]);
    *(float2*)(dst + 8 * 72 + 64 + 2 * cc) = make_float2(c[8][2], c[8][3]);
}

// ---------------------------------------------------------------------------
// kv_reduce: g_KVh[bh][d][e] = fp16( sum_p KVpart[bh][p][d][e] ), e in [0,72)
// ---------------------------------------------------------------------------
__global__ void kv_reduce()
{
    int gi = blockIdx.x * blockDim.x + threadIdx.x;
    const int TOT = BH_ * HD_ * 72;
    if (gi >= TOT) return;
    int bh = gi / (HD_ * 72);
    int r  = gi % (HD_ * 72);
    float s = 0.f;
#pragma unroll
    for (int p = 0; p < SPLIT_; p++)
        s += g_KVpart[((size_t)bh * SPLIT_ + p) * (HD_ * 72) + r];
    g_KVh[gi] = __float2half_rn(s);
}

// ---------------------------------------------------------------------------
// apply: out[s][e] = (Q . KV)/clip(Q . KS) via one fp16 MMA sweep (N=72,
// norm = col 64). Writes g_O fp16 pair-permuted. Block = 64 s-rows, 4 warps.
// ---------------------------------------------------------------------------
__global__ __launch_bounds__(128)
void apply_kernel()
{
    __shared__ __align__(16) __half Qs[64 * 72];
    __shared__ __align__(16) __half KVs[64 * 72];
    const int t = threadIdx.x, lane = t & 31, w = t >> 5;
    const int bh = blockIdx.y;
    const int b = bh >> 4, h = bh & 15;
    const int s0blk = blockIdx.x * 64;
    const uint32_t sQ = smem_u32(Qs), sKV = smem_u32(KVs);

    const __half* Qg = g_Qh + ((size_t)bh * S_ + s0blk) * HD_;
#pragma unroll
    for (int j = 0; j < 4; j++) {
        int q = t + j * 128, row = q >> 3, seg = q & 7;
        CP16(sQ + row * MPITCH + seg * 16, Qg + row * HD_ + seg * 8);
    }
    const __half* KVg = g_KVh + (size_t)bh * HD_ * 72;
#pragma unroll
    for (int j = 0; j < 5; j++) {
        int q = t + j * 128;
        if (q < 576) CP16(sKV + q * 16, KVg + q * 8);
    }
    CP_COMMIT();
    CP_WAIT0();
    __syncthreads();

    const int g = lane >> 2, cc = lane & 3;
    const int m0 = w * 16;
    const uint32_t aBase = sQ + (m0 + (lane & 7) + ((lane >> 3) & 1) * 8) * MPITCH
                         + ((lane >> 4) << 4);
    const uint32_t bBase = sKV + ((lane & 7) + ((lane >> 3) & 1) * 8) * MPITCH
                         + ((lane >> 4) << 4);
    const uint32_t b8Base = sKV + ((lane & 7) + ((lane >> 3) & 1) * 8) * MPITCH + 128;

    float c[9][4];
#pragma unroll
    for (int nt = 0; nt < 9; nt++)
#pragma unroll
        for (int r = 0; r < 4; r++) c[nt][r] = 0.f;

#pragma unroll
    for (int k0 = 0; k0 < 64; k0 += 16) {
        uint32_t af[4];
        LDSM_X4(af[0], af[1], af[2], af[3], aBase + k0 * 2);
#pragma unroll
        for (int nt2 = 0; nt2 < 4; nt2++) {
            uint32_t b0, b1, b2, b3;
            LDSM_X4_T(b0, b1, b2, b3, bBase + k0 * MPITCH + nt2 * 32);
            uint32_t bf0[2] = {b0, b1}, bf1[2] = {b2, b3};
            MMA_F16(c[2 * nt2],     af, bf0);
            MMA_F16(c[2 * nt2 + 1], af, bf1);
        }
        {   // norm tile (cols 64-71)
            uint32_t b0, b1;
            LDSM_X2_T(b0, b1, b8Base + k0 * MPITCH);
            uint32_t bf[2] = {b0, b1};
            MMA_F16(c[8], af, bf);
        }
    }

    float n1 = __shfl_sync(0xFFFFFFFFu, c[8][0], lane & ~3);
    float n2 = __shfl_sync(0xFFFFFFFFu, c[8][2], lane & ~3);
    n1 = 1.0f / (fmaxf(n1, 1.0f) + 1e-6f);
    n2 = 1.0f / (fmaxf(n2, 1.0f) + 1e-6f);

    const int row1 = s0blk + m0 + g;
    const int row2 = row1 + 8;
#pragma unroll
    for (int nt = 0; nt < 8; nt++) {
        int e = 8 * nt + 2 * cc;
        int j = (4 * nt + cc) & 7;                   // pair index within 16-group
        int pp = (j < 4) ? 2 * j : 2 * (j - 4) + 1;  // permuted pair slot
        int col = h * HD_ + (e & ~15) + 2 * pp;
        *(__half2*)(g_O + ((size_t)b * S_ + row1) * D_ + col) =
            __floats2half2_rn(c[nt][0] * n1, c[nt][1] * n1);
        *(__half2*)(g_O + ((size_t)b * S_ + row2) * D_ + col) =
            __floats2half2_rn(c[nt][2] * n2, c[nt][3] * n2);
    }
}

// ---------------------------------------------------------------------------
extern "C" void kernel_launch(void* const* d_in, const int* in_sizes, int n_in,
                              void* d_out, int out_size)
{
    (void)in_sizes; (void)n_in; (void)out_size;
    const float* query = (const float*)d_in[0];
    const float* key   = (const float*)d_in[1];
    const float* value = (const float*)d_in[2];
    const float* cosp  = (const float*)d_in[3];
    const float* sinp  = (const float*)d_in[4];
    const float* Wq = (const float*)d_in[5];
    const float* bq = (const float*)d_in[6];
    const float* Wk = (const float*)d_in[7];
    const float* bk = (const float*)d_in[8];
    const float* Wv = (const float*)d_in[9];
    const float* bv = (const float*)d_in[10];
    const float* Wo = (const float*)d_in[11];
    const float* bo = (const float*)d_in[12];
    float* out = (float*)d_out;

    cudaFuncSetAttribute(gemm_qkv, cudaFuncAttributeMaxDynamicSharedMemorySize, SMEM_BYTES);
    cudaFuncSetAttribute(gemm_out, cudaFuncAttributeMaxDynamicSharedMemorySize, SMEM_BYTES);
    cudaFuncSetAttribute(kv_kernel, cudaFuncAttributeMaxDynamicSharedMemorySize, 2 * 256 * MPITCH);

    conv_w_kernel<<<dim3((D_ * D_ / 16 + 255) / 256, 4), 256>>>(
        (const float4*)Wq, (const float4*)Wk, (const float4*)Wv, (const float4*)Wo);
    conv_act_kernel<<<dim3((M_ * D_ / 16 + 255) / 256, 3), 256>>>(
        (const float4*)query, (const float4*)key, (const float4*)value);

    gemm_qkv<<<dim3(D_ / TNN, M_ / TMM, 3), 256, SMEM_BYTES>>>(bq, bk, bv, cosp, sinp);

    kv_kernel<<<dim3(SPLIT_, BH_), 128, 2 * 256 * MPITCH>>>();
    kv_reduce<<<(BH_ * HD_ * 72 + 255) / 256, 256>>>();
    apply_kernel<<<dim3(S_ / 64, BH_), 128>>>();

    gemm_out<<<dim3(D_ / TNN, M_ / TMM), 256, SMEM_BYTES>>>(bo, out);
}

// round 14
// speedup vs baseline: 1.1482x; 1.1482x over previous
#include <cuda_runtime.h>
#include <cuda_fp16.h>
#include <cstdint>
#include <math.h>

#define B_ 4
#define S_ 4096
#define D_ 1024
#define H_ 16
#define HD_ 64
#define M_ (B_*S_)          // 16384
#define BH_ (B_*H_)         // 64
#define SPLIT_ 16

// GEMM tiling (fp16 mma.sync m16n8k16, fp32 accumulate) — R12 sweet spot
#define TM 128
#define TN 128
#define BKH 64                      // halves per K-chunk = 128B row
#define NCH (D_/BKH)                // 16 chunks
#define PITCHB 160                  // bytes per smem row (bank-clean)
#define STG_BYTES (128*PITCHB)      // 20480 per operand per stage
#define SMEM_BYTES (4*STG_BYTES)    // 2 stages x (A+B) = 81920 B -> 2 blocks/SM

// mid-section smem pitch: 144B per 72-half row -> conflict-free ldmatrix
#define MPITCH 144

// ---------------- scratch (device globals; no allocation) ----------------
__device__ __align__(16) __half g_Qh[(size_t)M_ * D_];  // [bh][s][d] fp16
__device__ __align__(16) __half g_Kh[(size_t)M_ * D_];
__device__ __align__(16) __half g_Vh[(size_t)M_ * D_];
__device__ __align__(16) __half g_O[(size_t)M_ * D_];   // [b,s,1024] fp16+perm
__device__ __align__(16) __half g_Ah[3][(size_t)M_ * D_]; // fp16+perm activations
__device__ __align__(16) __half g_Wh[4][(size_t)D_ * D_]; // fp16+perm weights
__device__ __align__(16) float  g_KVpart[(size_t)BH_ * SPLIT_ * HD_ * 72];
__device__ __align__(16) __half g_KVh[(size_t)BH_ * HD_ * 72]; // 0-63 KV, 64 KS

// ---------------- helpers ----------------
__device__ __forceinline__ uint32_t smem_u32(const void* p) {
    uint32_t a;
    asm("{ .reg .u64 t; cvta.to.shared.u64 t, %1; cvt.u32.u64 %0, t; }" : "=r"(a) : "l"(p));
    return a;
}
#define CP16(dst, src) asm volatile("cp.async.cg.shared.global [%0], [%1], 16;" :: "r"(dst), "l"(src))
#define CP_COMMIT()    asm volatile("cp.async.commit_group;" ::: "memory")
#define CP_WAIT1()     asm volatile("cp.async.wait_group 1;" ::: "memory")
#define CP_WAIT0()     asm volatile("cp.async.wait_group 0;" ::: "memory")

#define MMA_F16(c, a, b) \
    asm volatile("mma.sync.aligned.m16n8k16.row.col.f32.f16.f16.f32 " \
        "{%0,%1,%2,%3}, {%4,%5,%6,%7}, {%8,%9}, {%0,%1,%2,%3};" \
        : "+f"((c)[0]), "+f"((c)[1]), "+f"((c)[2]), "+f"((c)[3]) \
        : "r"((a)[0]), "r"((a)[1]), "r"((a)[2]), "r"((a)[3]), \
          "r"((b)[0]), "r"((b)[1]))

#define LDSM_X4(r0, r1, r2, r3, addr) \
    asm volatile("ldmatrix.sync.aligned.m8n8.x4.shared.b16 {%0,%1,%2,%3}, [%4];" \
        : "=r"(r0), "=r"(r1), "=r"(r2), "=r"(r3) : "r"(addr))
#define LDSM_X4_T(r0, r1, r2, r3, addr) \
    asm volatile("ldmatrix.sync.aligned.m8n8.x4.trans.shared.b16 {%0,%1,%2,%3}, [%4];" \
        : "=r"(r0), "=r"(r1), "=r"(r2), "=r"(r3) : "r"(addr))
#define LDSM_X2_T(r0, r1, addr) \
    asm volatile("ldmatrix.sync.aligned.m8n8.x2.trans.shared.b16 {%0,%1}, [%2];" \
        : "=r"(r0), "=r"(r1) : "r"(addr))

__device__ __forceinline__ uint32_t pack_h2(float lo, float hi) {
    __half2 h = __floats2half2_rn(lo, hi);
    return *reinterpret_cast<uint32_t*>(&h);
}

// ---------------------------------------------------------------------------
// fp32 -> fp16 RN + pair-permute within 16-groups: pairs out {0,4,1,5,2,6,3,7}
// ---------------------------------------------------------------------------
__device__ __forceinline__ void conv_body(const float4* __restrict__ src,
                                          uint4* __restrict__ dst, int i)
{
    float4 v0 = src[4 * i], v1 = src[4 * i + 1], v2 = src[4 * i + 2], v3 = src[4 * i + 3];
    uint4 o0, o1;
    o0.x = pack_h2(v0.x, v0.y);   o0.y = pack_h2(v2.x, v2.y);
    o0.z = pack_h2(v0.z, v0.w);   o0.w = pack_h2(v2.z, v2.w);
    o1.x = pack_h2(v1.x, v1.y);   o1.y = pack_h2(v3.x, v3.y);
    o1.z = pack_h2(v1.z, v1.w);   o1.w = pack_h2(v3.z, v3.w);
    dst[2 * i] = o0;  dst[2 * i + 1] = o1;
}

__global__ void conv_act_kernel(const float4* __restrict__ q, const float4* __restrict__ k,
                                const float4* __restrict__ v)
{
    int i = blockIdx.x * blockDim.x + threadIdx.x;
    const int n16 = M_ * D_ / 16;
    if (i < n16) {
        const float4* src = (blockIdx.y == 0) ? q : (blockIdx.y == 1) ? k : v;
        conv_body(src, (uint4*)(g_Ah[blockIdx.y]), i);
    }
}

__global__ void conv_w_kernel(const float4* __restrict__ w0, const float4* __restrict__ w1,
                              const float4* __restrict__ w2, const float4* __restrict__ w3)
{
    int i = blockIdx.x * blockDim.x + threadIdx.x;
    const int n16 = D_ * D_ / 16;
    if (i < n16) {
        const float4* src = (blockIdx.y == 0) ? w0 : (blockIdx.y == 1) ? w1
                          : (blockIdx.y == 2) ? w2 : w3;
        conv_body(src, (uint4*)(g_Wh[blockIdx.y]), i);
    }
}

// ---------------------------------------------------------------------------
// Shared 128x128 GEMM mainloop (R12): 2-stage cp.async, tail-drained.
// ---------------------------------------------------------------------------
__device__ __forceinline__ void gemm_mainloop(
    const __half* __restrict__ Ap, const __half* __restrict__ Wp,
    uint32_t sm_u, char* sm, int tid, int m0, int n0,
    int lane, int wid, float acc[4][4][4])
{
    const int wm64 = (wid & 1) * 64;
    const int wn8  = (wid >> 1) * 8;
    const int qrow = lane >> 2;
    const int qcol = lane & 3;

    auto load_chunk = [&](int ch, int st) {
        const int k0 = ch * BKH;
        const uint32_t aB = sm_u + (uint32_t)st * 2 * STG_BYTES;
        const uint32_t bB = aB + STG_BYTES;
#pragma unroll
        for (int j = 0; j < 4; j++) {
            int q = tid + j * 256, row = q >> 3, seg = q & 7;
            CP16(aB + (uint32_t)(row * PITCHB + seg * 16),
                 Ap + (size_t)(m0 + row) * D_ + k0 + seg * 8);
        }
#pragma unroll
        for (int j = 0; j < 4; j++) {
            int q = tid + j * 256, row = q >> 3, seg = q & 7;
            CP16(bB + (uint32_t)(row * PITCHB + seg * 16),
                 Wp + (size_t)(n0 + row) * D_ + k0 + seg * 8);
        }
    };

    load_chunk(0, 0); CP_COMMIT();
    load_chunk(1, 1); CP_COMMIT();

    for (int i = 0; i < NCH; i++) {
        if (i == NCH - 1) CP_WAIT0();    // tail: drain everything
        else              CP_WAIT1();
        __syncthreads();

        const int st = i & 1;
        const char* As = sm + (size_t)st * 2 * STG_BYTES;
        const char* Bs = As + STG_BYTES;
#pragma unroll
        for (int kk = 0; kk < 4; kk++) {
            uint32_t bf[4][2];
#pragma unroll
            for (int nt = 0; nt < 4; nt++) {
                uint2 bv = *(const uint2*)(Bs + (wn8 + nt * 32 + qrow) * PITCHB + kk * 32 + 8 * qcol);
                bf[nt][0] = bv.x;  bf[nt][1] = bv.y;
            }
#pragma unroll
            for (int mt = 0; mt < 4; mt++) {
                const char* ap = As + (wm64 + mt * 16 + qrow) * PITCHB + kk * 32 + 8 * qcol;
                uint2 alo = *(const uint2*)ap;
                uint2 ahi = *(const uint2*)(ap + 8 * PITCHB);
                uint32_t af[4] = {alo.x, ahi.x, alo.y, ahi.y};
#pragma unroll
                for (int nt = 0; nt < 4; nt++) MMA_F16(acc[mt][nt], af, bf[nt]);
            }
        }

        if (i + 2 < NCH) {
            __syncthreads();
            load_chunk(i + 2, st);
            CP_COMMIT();
        }
    }
}

// ---------------------------------------------------------------------------
// Fused QKV projection GEMM: blockIdx.z selects {Q,K,V}. R12 tiling.
// z=0/1: rope+elu -> g_Qh/g_Kh ; z=2: bias -> g_Vh
// ---------------------------------------------------------------------------
__global__ __launch_bounds__(256, 2)
void gemm_qkv(const float* __restrict__ bq, const float* __restrict__ bk,
              const float* __restrict__ bv,
              const float* __restrict__ cs, const float* __restrict__ sn)
{
    extern __shared__ __align__(16) char sm[];
    const int tid = threadIdx.x;
    const int z   = blockIdx.z;
    const int n0  = blockIdx.x * TN;
    const int m0  = blockIdx.y * TM;
    const int lane = tid & 31, wid = tid >> 5;
    const uint32_t sm_u = smem_u32(sm);
    const float* bias = (z == 0) ? bq : (z == 1) ? bk : bv;

    float acc[4][4][4];
#pragma unroll
    for (int mt = 0; mt < 4; mt++)
#pragma unroll
        for (int nt = 0; nt < 4; nt++)
#pragma unroll
            for (int r = 0; r < 4; r++) acc[mt][nt][r] = 0.f;

    gemm_mainloop(g_Ah[z], g_Wh[z], sm_u, sm, tid, m0, n0, lane, wid, acc);

    const int wm64 = (wid & 1) * 64;
    const int wn8  = (wid >> 1) * 8;
    const int qrow = lane >> 2;
    const int qcol = lane & 3;

#pragma unroll
    for (int mt = 0; mt < 4; mt++) {
#pragma unroll
        for (int r = 0; r < 4; r++) {
            const int row = wm64 + mt * 16 + qrow + (r >> 1) * 8;
            const int m = m0 + row;
            const int b = m >> 12;
            const int s = m & (S_ - 1);
            const int cc = 2 * qcol + (r & 1);

            if (z == 2) {
#pragma unroll
                for (int nt = 0; nt < 4; nt++) {
                    int col = wn8 + nt * 32 + cc;
                    int h = (n0 + col) >> 6, e = col & 63;
                    g_Vh[(((size_t)b * H_ + h) * S_ + s) * HD_ + e] =
                        __float2half_rn(acc[mt][nt][r] + bias[n0 + col]);
                }
            } else {
                __half* dstb = (z == 0) ? g_Qh : g_Kh;
#pragma unroll
                for (int half = 0; half < 2; half++) {
                    const int p = half * 2;
                    const int h = (n0 >> 6) + half;
                    const int j = wn8 + cc;                      // 0..31
                    float x1 = acc[mt][p][r]     + bias[h * HD_ + j];
                    float x2 = acc[mt][p + 1][r] + bias[h * HD_ + j + 32];
                    float c1 = cs[s * HD_ + j],      s1 = sn[s * HD_ + j];
                    float c2 = cs[s * HD_ + j + 32], s2 = sn[s * HD_ + j + 32];
                    float r1 = x1 * c1 - x2 * s1;
                    float r2 = x2 * c2 + x1 * s2;
                    r1 = (r1 > 0.f) ? (r1 + 1.f) : expf(r1);
                    r2 = (r2 > 0.f) ? (r2 + 1.f) : expf(r2);
                    __half* d = dstb + (((size_t)b * H_ + h) * S_ + s) * HD_;
                    d[j]      = __float2half_rn(fmaxf(r1, 0.01f));
                    d[j + 32] = __float2half_rn(fmaxf(r2, 0.01f));
                }
            }
        }
    }
}

// ---------------------------------------------------------------------------
// Output projection GEMM: out = g_O @ Wo^T + bo  (fp32 out). R12 tiling.
// ---------------------------------------------------------------------------
__global__ __launch_bounds__(256, 2)
void gemm_out(const float* __restrict__ bias, float* __restrict__ out)
{
    extern __shared__ __align__(16) char sm[];
    const int tid = threadIdx.x;
    const int n0  = blockIdx.x * TN;
    const int m0  = blockIdx.y * TM;
    const int lane = tid & 31, wid = tid >> 5;
    const uint32_t sm_u = smem_u32(sm);

    float acc[4][4][4];
#pragma unroll
    for (int mt = 0; mt < 4; mt++)
#pragma unroll
        for (int nt = 0; nt < 4; nt++)
#pragma unroll
            for (int r = 0; r < 4; r++) acc[mt][nt][r] = 0.f;

    gemm_mainloop(g_O, g_Wh[3], sm_u, sm, tid, m0, n0, lane, wid, acc);

    const int wm64 = (wid & 1) * 64;
    const int wn8  = (wid >> 1) * 8;
    const int qrow = lane >> 2;
    const int qcol = lane & 3;

#pragma unroll
    for (int mt = 0; mt < 4; mt++) {
#pragma unroll
        for (int r = 0; r < 4; r++) {
            const int row = wm64 + mt * 16 + qrow + (r >> 1) * 8;
            const int m = m0 + row;
            const int cc = 2 * qcol + (r & 1);
#pragma unroll
            for (int nt = 0; nt < 4; nt++) {
                int col = wn8 + nt * 32 + cc;
                out[(size_t)m * D_ + n0 + col] = acc[mt][nt][r] + bias[n0 + col];
            }
        }
    }
}

// ---------------------------------------------------------------------------
// kv_kernel: KVpart[bh][sp][d][e] = sum_{s in chunk} K[s][d] * V'[s][e]
// where V' = [V | 1 | 0...0] (ones column 64 -> KS computed by the same MMA).
// ---------------------------------------------------------------------------
__global__ __launch_bounds__(128)
void kv_kernel()
{
    extern __shared__ __align__(16) char kvsm[];
    const int t = threadIdx.x, lane = t & 31, w = t >> 5;
    const int bh = blockIdx.y, sp = blockIdx.x;
    const uint32_t sK = smem_u32(kvsm);
    const uint32_t sV = sK + 256 * MPITCH;

    const __half* Kg = g_Kh + ((size_t)bh * S_ + sp * 256) * HD_;
    const __half* Vg = g_Vh + ((size_t)bh * S_ + sp * 256) * HD_;
#pragma unroll
    for (int j = 0; j < 16; j++) {
        int q = t + j * 128, row = q >> 3, seg = q & 7;
        CP16(sK + row * MPITCH + seg * 16, Kg + row * HD_ + seg * 8);
        CP16(sV + row * MPITCH + seg * 16, Vg + row * HD_ + seg * 8);
    }
    {   // V pad: col 64 = 1.0h, cols 65-71 = 0
        uint4 ones = make_uint4(0x00003C00u, 0u, 0u, 0u);
        *(uint4*)(kvsm + (256 * MPITCH) + (t * 2) * MPITCH + 128) = ones;
        *(uint4*)(kvsm + (256 * MPITCH) + (t * 2 + 1) * MPITCH + 128) = ones;
    }
    CP_COMMIT();
    CP_WAIT0();
    __syncthreads();

    const int g = lane >> 2, cc = lane & 3;
    const int d0 = w * 16;
    const uint32_t aBase = sK + ((lane & 7) + ((lane >> 4) << 3)) * MPITCH
                         + d0 * 2 + ((lane >> 3) & 1) * 16;
    const uint32_t bBase = sV + ((lane & 7) + ((lane >> 3) & 1) * 8) * MPITCH
                         + ((lane >> 4) << 4);
    const uint32_t b8Base = sV + ((lane & 7) + ((lane >> 3) & 1) * 8) * MPITCH + 128;

    float c[9][4];
#pragma unroll
    for (int nt = 0; nt < 9; nt++)
#pragma unroll
        for (int r = 0; r < 4; r++) c[nt][r] = 0.f;

#pragma unroll 4
    for (int s0 = 0; s0 < 256; s0 += 16) {
        uint32_t af[4];
        LDSM_X4_T(af[0], af[1], af[2], af[3], aBase + s0 * MPITCH);
#pragma unroll
        for (int nt2 = 0; nt2 < 4; nt2++) {
            uint32_t b0, b1, b2, b3;
            LDSM_X4_T(b0, b1, b2, b3, bBase + s0 * MPITCH + nt2 * 32);
            uint32_t bf0[2] = {b0, b1}, bf1[2] = {b2, b3};
            MMA_F16(c[2 * nt2],     af, bf0);
            MMA_F16(c[2 * nt2 + 1], af, bf1);
        }
        {   // KS tile (cols 64-71; col 64 = ones)
            uint32_t b0, b1;
            LDSM_X2_T(b0, b1, b8Base + s0 * MPITCH);
            uint32_t bf[2] = {b0, b1};
            MMA_F16(c[8], af, bf);
        }
    }

    float* dst = g_KVpart + (((size_t)bh * SPLIT_ + sp) * HD_ + d0 + g) * 72;
#pragma unroll
    for (int nt = 0; nt < 8; nt++) {
        *(float2*)(dst + 8 * nt + 2 * cc) = make_float2(c[nt][0], c[nt][1]);
        *(float2*)(dst + 8 * 72 + 8 * nt + 2 * cc) = make_float2(c[nt][2], c[nt][3]);
    }
    *(float2*)(dst + 64 + 2 * cc) = make_float2(c[8][0], c[8][1]);
    *(float2*)(dst + 8 * 72 + 64 + 2 * cc) = make_float2(c[8][2], c[8][3]);
}

// ---------------------------------------------------------------------------
// kv_reduce: g_KVh[bh][d][e] = fp16( sum_p KVpart[bh][p][d][e] ), e in [0,72)
// ---------------------------------------------------------------------------
__global__ void kv_reduce()
{
    int gi = blockIdx.x * blockDim.x + threadIdx.x;
    const int TOT = BH_ * HD_ * 72;
    if (gi >= TOT) return;
    int bh = gi / (HD_ * 72);
    int r  = gi % (HD_ * 72);
    float s = 0.f;
#pragma unroll
    for (int p = 0; p < SPLIT_; p++)
        s += g_KVpart[((size_t)bh * SPLIT_ + p) * (HD_ * 72) + r];
    g_KVh[gi] = __float2half_rn(s);
}

// ---------------------------------------------------------------------------
// apply: out[s][e] = (Q . KV)/clip(Q . KS) via one fp16 MMA sweep (N=72,
// norm = col 64). Writes g_O fp16 pair-permuted. Block = 64 s-rows, 4 warps.
// ---------------------------------------------------------------------------
__global__ __launch_bounds__(128)
void apply_kernel()
{
    __shared__ __align__(16) __half Qs[64 * 72];
    __shared__ __align__(16) __half KVs[64 * 72];
    const int t = threadIdx.x, lane = t & 31, w = t >> 5;
    const int bh = blockIdx.y;
    const int b = bh >> 4, h = bh & 15;
    const int s0blk = blockIdx.x * 64;
    const uint32_t sQ = smem_u32(Qs), sKV = smem_u32(KVs);

    const __half* Qg = g_Qh + ((size_t)bh * S_ + s0blk) * HD_;
#pragma unroll
    for (int j = 0; j < 4; j++) {
        int q = t + j * 128, row = q >> 3, seg = q & 7;
        CP16(sQ + row * MPITCH + seg * 16, Qg + row * HD_ + seg * 8);
    }
    const __half* KVg = g_KVh + (size_t)bh * HD_ * 72;
#pragma unroll
    for (int j = 0; j < 5; j++) {
        int q = t + j * 128;
        if (q < 576) CP16(sKV + q * 16, KVg + q * 8);
    }
    CP_COMMIT();
    CP_WAIT0();
    __syncthreads();

    const int g = lane >> 2, cc = lane & 3;
    const int m0 = w * 16;
    const uint32_t aBase = sQ + (m0 + (lane & 7) + ((lane >> 3) & 1) * 8) * MPITCH
                         + ((lane >> 4) << 4);
    const uint32_t bBase = sKV + ((lane & 7) + ((lane >> 3) & 1) * 8) * MPITCH
                         + ((lane >> 4) << 4);
    const uint32_t b8Base = sKV + ((lane & 7) + ((lane >> 3) & 1) * 8) * MPITCH + 128;

    float c[9][4];
#pragma unroll
    for (int nt = 0; nt < 9; nt++)
#pragma unroll
        for (int r = 0; r < 4; r++) c[nt][r] = 0.f;

#pragma unroll
    for (int k0 = 0; k0 < 64; k0 += 16) {
        uint32_t af[4];
        LDSM_X4(af[0], af[1], af[2], af[3], aBase + k0 * 2);
#pragma unroll
        for (int nt2 = 0; nt2 < 4; nt2++) {
            uint32_t b0, b1, b2, b3;
            LDSM_X4_T(b0, b1, b2, b3, bBase + k0 * MPITCH + nt2 * 32);
            uint32_t bf0[2] = {b0, b1}, bf1[2] = {b2, b3};
            MMA_F16(c[2 * nt2],     af, bf0);
            MMA_F16(c[2 * nt2 + 1], af, bf1);
        }
        {   // norm tile (cols 64-71)
            uint32_t b0, b1;
            LDSM_X2_T(b0, b1, b8Base + k0 * MPITCH);
            uint32_t bf[2] = {b0, b1};
            MMA_F16(c[8], af, bf);
        }
    }

    float n1 = __shfl_sync(0xFFFFFFFFu, c[8][0], lane & ~3);
    float n2 = __shfl_sync(0xFFFFFFFFu, c[8][2], lane & ~3);
    n1 = 1.0f / (fmaxf(n1, 1.0f) + 1e-6f);
    n2 = 1.0f / (fmaxf(n2, 1.0f) + 1e-6f);

    const int row1 = s0blk + m0 + g;
    const int row2 = row1 + 8;
#pragma unroll
    for (int nt = 0; nt < 8; nt++) {
        int e = 8 * nt + 2 * cc;
        int j = (4 * nt + cc) & 7;                   // pair index within 16-group
        int pp = (j < 4) ? 2 * j : 2 * (j - 4) + 1;  // permuted pair slot
        int col = h * HD_ + (e & ~15) + 2 * pp;
        *(__half2*)(g_O + ((size_t)b * S_ + row1) * D_ + col) =
            __floats2half2_rn(c[nt][0] * n1, c[nt][1] * n1);
        *(__half2*)(g_O + ((size_t)b * S_ + row2) * D_ + col) =
            __floats2half2_rn(c[nt][2] * n2, c[nt][3] * n2);
    }
}

// ---------------------------------------------------------------------------
extern "C" void kernel_launch(void* const* d_in, const int* in_sizes, int n_in,
                              void* d_out, int out_size)
{
    (void)in_sizes; (void)n_in; (void)out_size;
    const float* query = (const float*)d_in[0];
    const float* key   = (const float*)d_in[1];
    const float* value = (const float*)d_in[2];
    const float* cosp  = (const float*)d_in[3];
    const float* sinp  = (const float*)d_in[4];
    const float* Wq = (const float*)d_in[5];
    const float* bq = (const float*)d_in[6];
    const float* Wk = (const float*)d_in[7];
    const float* bk = (const float*)d_in[8];
    const float* Wv = (const float*)d_in[9];
    const float* bv = (const float*)d_in[10];
    const float* Wo = (const float*)d_in[11];
    const float* bo = (const float*)d_in[12];
    float* out = (float*)d_out;

    cudaFuncSetAttribute(gemm_qkv, cudaFuncAttributeMaxDynamicSharedMemorySize, SMEM_BYTES);
    cudaFuncSetAttribute(gemm_out, cudaFuncAttributeMaxDynamicSharedMemorySize, SMEM_BYTES);
    cudaFuncSetAttribute(kv_kernel, cudaFuncAttributeMaxDynamicSharedMemorySize, 2 * 256 * MPITCH);

    conv_w_kernel<<<dim3((D_ * D_ / 16 + 255) / 256, 4), 256>>>(
        (const float4*)Wq, (const float4*)Wk, (const float4*)Wv, (const float4*)Wo);
    conv_act_kernel<<<dim3((M_ * D_ / 16 + 255) / 256, 3), 256>>>(
        (const float4*)query, (const float4*)key, (const float4*)value);

    gemm_qkv<<<dim3(D_ / TN, M_ / TM, 3), 256, SMEM_BYTES>>>(bq, bk, bv, cosp, sinp);

    kv_kernel<<<dim3(SPLIT_, BH_), 128, 2 * 256 * MPITCH>>>();
    kv_reduce<<<(BH_ * HD_ * 72 + 255) / 256, 256>>>();
    apply_kernel<<<dim3(S_ / 64, BH_), 128>>>();

    gemm_out<<<dim3(D_ / TN, M_ / TM), 256, SMEM_BYTES>>>(bo, out);
}